// round 13
// baseline (speedup 1.0000x reference)
#include <cuda_runtime.h>
#include <cuda_fp16.h>
#include <cstdint>
#include <math.h>

#define T_STEPS 16
#define BATCH   128
#define IN_DIM  12288
#define HH1     256
#define HH2     512

// ---------------- scratch (static __device__ globals; no runtime alloc) ----
__device__ float g_pre1[T_STEPS * BATCH * 4 * HH1];   //  8.4 MB
__device__ float g_pre2[T_STEPS * BATCH * 4 * HH2];   // 16.8 MB

// fp16 staging: A split (hi,lo), W rounded once
__device__ __half g_Ahi[T_STEPS * BATCH * IN_DIM];    // 50 MB
__device__ __half g_Alo[T_STEPS * BATCH * IN_DIM];    // 50 MB
__device__ __half g_Wf [4 * HH1 * IN_DIM];            // 25 MB
__device__ __half g_Y1hi[T_STEPS * BATCH * HH1];      //  1 MB
__device__ __half g_Y1lo[T_STEPS * BATCH * HH1];      //  1 MB
__device__ __half g_W2f[4 * HH2 * HH1];               //  1 MB

// per-quarter h staging for tensorized layer-2 recurrence
__device__ __half g_H2hi[4 * 32 * HH2];
__device__ __half g_H2lo[4 * 32 * HH2];

// quarter-local barrier state (stride 32 u32 = 128 B to avoid false sharing)
__device__ unsigned g_bcnt[4 * 32];
__device__ unsigned g_bgen[4 * 32];

// ===========================================================================
// helpers
// ===========================================================================
__device__ __forceinline__ uint32_t smem_u32(const void* p) {
    uint32_t a;
    asm("{ .reg .u64 t; cvta.to.shared.u64 t, %1; cvt.u32.u64 %0, t; }"
        : "=r"(a) : "l"(p));
    return a;
}

#define LDSM_X4(r, addr) \
    asm volatile("ldmatrix.sync.aligned.m8n8.x4.shared.b16 {%0,%1,%2,%3}, [%4];" \
        : "=r"((r)[0]), "=r"((r)[1]), "=r"((r)[2]), "=r"((r)[3]) : "r"(addr))

#define MMA16816H(d, a, b0v, b1v) \
    asm volatile("mma.sync.aligned.m16n8k16.row.col.f32.f16.f16.f32 " \
        "{%0,%1,%2,%3}, {%4,%5,%6,%7}, {%8,%9}, {%0,%1,%2,%3};" \
        : "+f"((d)[0]), "+f"((d)[1]), "+f"((d)[2]), "+f"((d)[3]) \
        : "r"((a)[0]), "r"((a)[1]), "r"((a)[2]), "r"((a)[3]), \
          "r"(b0v), "r"(b1v))

#define CP_ASYNC16(dst, src) \
    asm volatile("cp.async.cg.shared.global [%0], [%1], 16;" \
        :: "r"(dst), "l"(src))
#define CP_COMMIT() asm volatile("cp.async.commit_group;" ::: "memory")
#define CP_WAIT0()  asm volatile("cp.async.wait_group 0;"  ::: "memory")
#define CP_WAIT2()  asm volatile("cp.async.wait_group 2;"  ::: "memory")

// quarter-local device barrier over nblocks co-resident blocks
__device__ __forceinline__ void grid_sync_q(unsigned& lgen, unsigned* cnt,
                                            unsigned* gen, int nblocks) {
    __syncthreads();
    if (threadIdx.x == 0) {
        __threadfence();
        unsigned a = atomicAdd(cnt, 1);
        if (a == (unsigned)(nblocks - 1)) {
            *cnt = 0;
            __threadfence();
            atomicAdd(gen, 1);
        } else {
            while (*(volatile unsigned*)gen <= lgen) { }
            __threadfence();
        }
        lgen++;
    }
    __syncthreads();
}

// ===========================================================================
// fp32 -> (hi, lo) fp16 split / fp32 -> fp16 round
// ===========================================================================
__global__ __launch_bounds__(256)
void split_f16(const float* __restrict__ x, __half* __restrict__ hi,
               __half* __restrict__ lo, int n4) {
    int i = blockIdx.x * blockDim.x + threadIdx.x;
    if (i >= n4) return;
    float4 v = ((const float4*)x)[i];
    float vv[4] = {v.x, v.y, v.z, v.w};
    __align__(8) __half h[4], l[4];
#pragma unroll
    for (int j = 0; j < 4; j++) {
        h[j] = __float2half_rn(vv[j]);
        l[j] = __float2half_rn(vv[j] - __half2float(h[j]));
    }
    ((uint2*)hi)[i] = *(uint2*)h;
    ((uint2*)lo)[i] = *(uint2*)l;
}

__global__ __launch_bounds__(256)
void conv_f16(const float* __restrict__ x, __half* __restrict__ w, int n4) {
    int i = blockIdx.x * blockDim.x + threadIdx.x;
    if (i >= n4) return;
    float4 v = ((const float4*)x)[i];
    __align__(8) __half h[4] = { __float2half_rn(v.x), __float2half_rn(v.y),
                                 __float2half_rn(v.z), __float2half_rn(v.w) };
    ((uint2*)w)[i] = *(uint2*)h;
}

// ===========================================================================
// fp16 2-pass GEMM on mma.sync:  C[M,N] = (Ahi+Alo)[M,K] @ Wf[N,K]^T + bias[N]
// 64x128 CTA tile, 128 threads, 2 CTAs/SM. BK=64 (128B rows, XOR-8 swizzle),
// 3-stage cp.async (32 KB/stage). 4 warps as 2m x 2n, warp tile 32x64.
// ===========================================================================
#define A_T_BYTES  8192                  // 64x64 fp16
#define W_T_BYTES  16384                 // 128x64 fp16
#define STAGE_B    (2 * A_T_BYTES + W_T_BYTES)       // 32 KB
#define GEMM_SMEM  (3 * STAGE_B)                     // 96 KB

__global__ __launch_bounds__(128, 2)
void gemm_mma_f16(const __half* __restrict__ Ahi,
                  const __half* __restrict__ Alo,
                  const __half* __restrict__ Wf,
                  const float* __restrict__ bias,
                  float* __restrict__ C,
                  int N, int K)
{
    extern __shared__ __align__(1024) char smem[];
    const uint32_t sb = smem_u32(smem);

    const int tid  = threadIdx.x;
    const int lane = tid & 31;
    const int wid  = tid >> 5;
    const int wm   = wid & 1;            // 2 m halves (32 rows each)
    const int wn   = wid >> 1;           // 2 n halves (64 cols each)
    const int bm0 = blockIdx.y * 64;
    const int bn0 = blockIdx.x * 128;

    const __half* srcA[2] = { Ahi + (size_t)bm0 * K,  Alo + (size_t)bm0 * K };
    const __half* srcW    =   Wf  + (size_t)bn0 * K;

    const int NC = K / 64;

    auto issue_stage = [&](int kc, int stage) {
        const size_t koff = (size_t)kc * 64;
        const uint32_t stb = sb + stage * STAGE_B;
        // A tiles: 64 rows -> 512 16B chunks each
#pragma unroll
        for (int t = 0; t < 2; t++) {
            const uint32_t tb = stb + t * A_T_BYTES;
#pragma unroll
            for (int i = 0; i < 4; i++) {
                int idx = tid + i * 128;
                int rr = idx >> 3, c16 = idx & 7;
                const __half* src = srcA[t] + (size_t)rr * K + koff + c16 * 8;
                CP_ASYNC16(tb + rr * 128 + ((c16 ^ (rr & 7)) * 16), src);
            }
        }
        // W tile: 128 rows -> 1024 chunks
        {
            const uint32_t tb = stb + 2 * A_T_BYTES;
#pragma unroll
            for (int i = 0; i < 8; i++) {
                int idx = tid + i * 128;
                int rr = idx >> 3, c16 = idx & 7;
                const __half* src = srcW + (size_t)rr * K + koff + c16 * 8;
                CP_ASYNC16(tb + rr * 128 + ((c16 ^ (rr & 7)) * 16), src);
            }
        }
    };

    float acc[2][8][4];
#pragma unroll
    for (int mt = 0; mt < 2; mt++)
#pragma unroll
        for (int nt = 0; nt < 8; nt++)
#pragma unroll
            for (int j = 0; j < 4; j++)
                acc[mt][nt][j] = 0.f;

    const int arow  = wm * 32 + (lane & 15);
    const int ahalf = lane >> 4;
    const int brow  = wn * 64 + ((lane >> 4) << 3) + (lane & 7);
    const int bhalf = (lane >> 3) & 1;

    issue_stage(0, 0); CP_COMMIT();
    issue_stage(1, 1); CP_COMMIT();

#pragma unroll 1
    for (int kc = 0; kc < NC; kc++) {
        if (kc + 2 < NC) issue_stage(kc + 2, (kc + 2) % 3);
        CP_COMMIT();
        CP_WAIT2();
        __syncthreads();

        const uint32_t stb = sb + (kc % 3) * STAGE_B;
        const uint32_t tAh = stb;
        const uint32_t tAl = stb + A_T_BYTES;
        const uint32_t tW  = stb + 2 * A_T_BYTES;

#pragma unroll
        for (int ks = 0; ks < 4; ks++) {
            uint32_t ahi[2][4], alo[2][4], bf[4][4];
#pragma unroll
            for (int mt = 0; mt < 2; mt++) {
                int r  = arow;                       // 32-row warp strip
                int rr = r + mt * 16;
                int ch = 2 * ks + ahalf;
                uint32_t off = rr * 128 + ((ch ^ (rr & 7)) * 16);
                LDSM_X4(ahi[mt], tAh + off);
                LDSM_X4(alo[mt], tAl + off);
            }
#pragma unroll
            for (int nt2 = 0; nt2 < 4; nt2++) {
                int r  = brow + nt2 * 16;
                int ch = 2 * ks + bhalf;
                uint32_t off = r * 128 + ((ch ^ (r & 7)) * 16);
                LDSM_X4(bf[nt2], tW + off);
            }
#pragma unroll
            for (int mt = 0; mt < 2; mt++)
#pragma unroll
                for (int nt = 0; nt < 8; nt++) {
                    const uint32_t* bv = &bf[nt >> 1][(nt & 1) * 2];
                    MMA16816H(acc[mt][nt], ahi[mt], bv[0], bv[1]);
                    MMA16816H(acc[mt][nt], alo[mt], bv[0], bv[1]);
                }
        }
        __syncthreads();
    }

#pragma unroll
    for (int mt = 0; mt < 2; mt++) {
        int row0 = bm0 + wm * 32 + mt * 16 + (lane >> 2);
#pragma unroll
        for (int nt = 0; nt < 8; nt++) {
            int col = bn0 + wn * 64 + nt * 8 + (lane & 3) * 2;
            float b0 = bias[col], b1 = bias[col + 1];
            float2 o0 = { acc[mt][nt][0] + b0, acc[mt][nt][1] + b1 };
            float2 o1 = { acc[mt][nt][2] + b0, acc[mt][nt][3] + b1 };
            *(float2*)&C[(size_t)row0 * N + col]       = o0;
            *(float2*)&C[(size_t)(row0 + 8) * N + col] = o1;
        }
    }
}

// ===========================================================================
// Persistent layer-1 recurrence, TENSORIZED (3-pass fp16 split).
// Grid 128 = 4 batch-quarters x 32 unit-groups (8 units each).
// Block 256 thr; warps 0-3 do mma as 2m x 2n (warp 16b x 16row).
// Per step: G[32b x 32row] = Hq[32x256](hi,lo) @ Wg[32x256](hi,lo)^T,
// passes Hhi*Whi + Hhi*Wlo + Hlo*Whi. W stationary in smem; h staged
// from y1hi/y1lo global via cp.async (quarter-local barrier orders steps).
// ===========================================================================
#define R1_W_B (4 * 32 * 128)            // 16 KB per W component
#define R1_H_B (4 * 32 * 128)            // 16 KB per h component
#define REC1_SMEM (2 * R1_W_B + 2 * R1_H_B + 32 * 33 * 4)   // 69760 B

__global__ __launch_bounds__(256, 1)
void lstm_rec1_mma(const float* __restrict__ pre,   // [16][128][1024]
                   const float* __restrict__ Whh,   // [1024][256]
                   __half* __restrict__ y1hi,       // [16][128][256]
                   __half* __restrict__ y1lo)
{
    extern __shared__ __align__(1024) char sm1[];
    const uint32_t sb   = smem_u32(sm1);
    const uint32_t sWhi = sb;
    const uint32_t sWlo = sb + R1_W_B;
    const uint32_t sHhi = sb + 2 * R1_W_B;
    const uint32_t sHlo = sb + 2 * R1_W_B + R1_H_B;
    float* G = (float*)(sm1 + 2 * R1_W_B + 2 * R1_H_B);   // [32][33]

    const int tid  = threadIdx.x;
    const int lane = tid & 31;
    const int wid  = tid >> 5;
    const int wm   = wid & 1;            // batch half (16 each)
    const int wn   = (wid >> 1) & 1;     // gate-row half (16 each)
    const int bq   = blockIdx.x >> 5;
    const int ug   = blockIdx.x & 31;
    const int u0   = ug * 8;
    const int b0   = bq * 32;

    // stationary W: rows r = g*8+uu (32 rows x 256 cols), split fp16 hi/lo
    for (int i = tid; i < 1024; i += 256) {           // 16B chunks
        int r  = i >> 5;                              // row 0..31
        int ch = i & 31;                              // chunk 0..31
        int g = r >> 3, uu = r & 7;
        const float* wsrc = Whh + (size_t)(g * HH1 + u0 + uu) * HH1 + ch * 8;
        __align__(16) __half hi8[8], lo8[8];
#pragma unroll
        for (int j = 0; j < 8; j++) {
            float f = wsrc[j];
            hi8[j] = __float2half_rn(f);
            lo8[j] = __float2half_rn(f - __half2float(hi8[j]));
        }
        int kc = ch >> 3, c8 = ch & 7;
        uint32_t off = kc * (32 * 128) + r * 128 + ((c8 ^ (r & 7)) * 16);
        *(uint4*)(sm1 + (sWhi - sb) + off) = *(uint4*)hi8;
        *(uint4*)(sm1 + (sWlo - sb) + off) = *(uint4*)lo8;
    }
    unsigned lgen = 0;
    if (tid == 0) lgen = *(volatile unsigned*)&g_bgen[bq * 32];
    __syncthreads();

    const int u  = tid & 7;
    const int bl = tid >> 3;
    float c = 0.f;

    const int arow  = wm * 16 + (lane & 15);
    const int ahalf = lane >> 4;
    const int brow  = wn * 16 + ((lane >> 4) << 3) + (lane & 7);
    const int bhalf = (lane >> 3) & 1;

#pragma unroll 1
    for (int t = 0; t < T_STEPS; t++) {
        const float* prow = pre + ((size_t)t * BATCH + b0 + bl) * (4 * HH1) + u0 + u;
        float p0 = prow[0], p1 = prow[HH1], p2 = prow[2 * HH1], p3 = prow[3 * HH1];

        if (t > 0) {
            const __half* hsh = y1hi + ((size_t)(t - 1) * BATCH + b0) * HH1;
            const __half* hsl = y1lo + ((size_t)(t - 1) * BATCH + b0) * HH1;
#pragma unroll
            for (int i = 0; i < 4; i++) {
                int flat = tid + i * 256;             // 0..1023
                int row = flat >> 5;                  // batch 0..31
                int ch  = flat & 31;
                int kc = ch >> 3, c8 = ch & 7;
                uint32_t off = kc * (32 * 128) + row * 128 + ((c8 ^ (row & 7)) * 16);
                CP_ASYNC16(sHhi + off, hsh + row * HH1 + ch * 8);
                CP_ASYNC16(sHlo + off, hsl + row * HH1 + ch * 8);
            }
            CP_COMMIT(); CP_WAIT0();
            __syncthreads();

            if (wid < 4) {
                float acc[2][4];
#pragma unroll
                for (int nt = 0; nt < 2; nt++)
#pragma unroll
                    for (int j = 0; j < 4; j++) acc[nt][j] = 0.f;

#pragma unroll 4
                for (int ks = 0; ks < 16; ks++) {
                    const int kc = ks >> 2;
                    uint32_t ah[4], al[4], bh[4], bl2[4];
                    {
                        int ch = 2 * (ks & 3) + ahalf;
                        uint32_t off = kc * (32 * 128) + arow * 128 + ((ch ^ (arow & 7)) * 16);
                        LDSM_X4(ah, sHhi + off);
                        LDSM_X4(al, sHlo + off);
                    }
                    {
                        int ch = 2 * (ks & 3) + bhalf;
                        uint32_t off = kc * (32 * 128) + brow * 128 + ((ch ^ (brow & 7)) * 16);
                        LDSM_X4(bh, sWhi + off);
                        LDSM_X4(bl2, sWlo + off);
                    }
#pragma unroll
                    for (int nt = 0; nt < 2; nt++) {
                        MMA16816H(acc[nt], ah, bh[nt * 2], bh[nt * 2 + 1]);
                        MMA16816H(acc[nt], ah, bl2[nt * 2], bl2[nt * 2 + 1]);
                        MMA16816H(acc[nt], al, bh[nt * 2], bh[nt * 2 + 1]);
                    }
                }
#pragma unroll
                for (int nt = 0; nt < 2; nt++) {
                    int col = wn * 16 + nt * 8 + (lane & 3) * 2;
                    int row = wm * 16 + (lane >> 2);
                    G[col * 33 + row]           = acc[nt][0];
                    G[(col + 1) * 33 + row]     = acc[nt][1];
                    G[col * 33 + row + 8]       = acc[nt][2];
                    G[(col + 1) * 33 + row + 8] = acc[nt][3];
                }
            }
            __syncthreads();
        }

        float a0 = 0.f, a1 = 0.f, a2 = 0.f, a3 = 0.f;
        if (t > 0) {
            a0 = G[(0 * 8 + u) * 33 + bl];
            a1 = G[(1 * 8 + u) * 33 + bl];
            a2 = G[(2 * 8 + u) * 33 + bl];
            a3 = G[(3 * 8 + u) * 33 + bl];
        }

        float gi = p0 + a0, gf = p1 + a1, gg = p2 + a2, go = p3 + a3;
        float si = 1.f / (1.f + __expf(-gi));
        float sf = 1.f / (1.f + __expf(-gf));
        float so = 1.f / (1.f + __expf(-go));
        float tg = tanhf(gg);
        c = sf * c + si * tg;
        float h = so * tanhf(c);

        size_t oi = ((size_t)t * BATCH + b0 + bl) * HH1 + u0 + u;
        __half hb = __float2half_rn(h);
        y1hi[oi] = hb;
        y1lo[oi] = __float2half_rn(h - __half2float(hb));

        if (t < T_STEPS - 1)
            grid_sync_q(lgen, &g_bcnt[bq * 32], &g_bgen[bq * 32], 32);
    }
}

// ===========================================================================
// Persistent layer-2 recurrence, TENSORIZED (unchanged from R12)
// ===========================================================================
#define RC2_W_B (8 * 64 * 128)           // 64 KB per W component
#define RC2_H_B (8 * 32 * 128)           // 32 KB per h component
#define REC2_SMEM (2 * RC2_W_B + 2 * RC2_H_B + 64 * 33 * 4)   // 205056 B

__global__ __launch_bounds__(256, 1)
void lstm_rec2_mma(const float* __restrict__ pre,   // [16][128][2048]
                   const float* __restrict__ Whh,   // [2048][512]
                   float* __restrict__ out,         // [16][128][512]
                   __half* __restrict__ h2hi,       // [4][32][512]
                   __half* __restrict__ h2lo)
{
    extern __shared__ __align__(1024) char sm2[];
    const uint32_t sb   = smem_u32(sm2);
    const uint32_t sWhi = sb;
    const uint32_t sWlo = sb + RC2_W_B;
    const uint32_t sHhi = sb + 2 * RC2_W_B;
    const uint32_t sHlo = sb + 2 * RC2_W_B + RC2_H_B;
    float* G = (float*)(sm2 + 2 * RC2_W_B + 2 * RC2_H_B);   // [64][33]

    const int tid  = threadIdx.x;
    const int lane = tid & 31;
    const int wid  = tid >> 5;
    const int wm   = wid & 1;
    const int wn   = wid >> 1;
    const int bq   = blockIdx.x >> 5;
    const int ug   = blockIdx.x & 31;
    const int u0   = ug * 16;
    const int b0   = bq * 32;

    __half* h2hi_q = h2hi + (size_t)bq * 32 * HH2;
    __half* h2lo_q = h2lo + (size_t)bq * 32 * HH2;

    for (int i = tid; i < 4096; i += 256) {
        int r  = i >> 6;
        int ch = i & 63;
        int g = r >> 4, uu = r & 15;
        const float* wsrc = Whh + (size_t)(g * HH2 + u0 + uu) * HH2 + ch * 8;
        __align__(16) __half hi8[8], lo8[8];
#pragma unroll
        for (int j = 0; j < 8; j++) {
            float f = wsrc[j];
            hi8[j] = __float2half_rn(f);
            lo8[j] = __float2half_rn(f - __half2float(hi8[j]));
        }
        int kc = ch >> 3, c8 = ch & 7;
        uint32_t off = kc * (64 * 128) + r * 128 + ((c8 ^ (r & 7)) * 16);
        *(uint4*)(sm2 + (sWhi - sb) + off) = *(uint4*)hi8;
        *(uint4*)(sm2 + (sWlo - sb) + off) = *(uint4*)lo8;
    }
    unsigned lgen = 0;
    if (tid == 0) lgen = *(volatile unsigned*)&g_bgen[bq * 32];
    __syncthreads();

    const int u  = tid & 15;
    const int bb = tid >> 4;
    float c0 = 0.f, c1 = 0.f;

    const int arow  = wm * 16 + (lane & 15);
    const int ahalf = lane >> 4;
    const int brow  = wn * 16 + ((lane >> 4) << 3) + (lane & 7);
    const int bhalf = (lane >> 3) & 1;

#pragma unroll 1
    for (int t = 0; t < T_STEPS; t++) {
        const float* prowA = pre + ((size_t)t * BATCH + b0 + bb) * (4 * HH2) + u0 + u;
        const float* prowB = prowA + (size_t)16 * 4 * HH2;
        float pA[4], pB[4];
#pragma unroll
        for (int g = 0; g < 4; g++) { pA[g] = prowA[g * HH2]; pB[g] = prowB[g * HH2]; }

        if (t > 0) {
#pragma unroll
            for (int i = 0; i < 8; i++) {
                int flat = tid + i * 256;
                int row = flat >> 6;
                int ch  = flat & 63;
                int kc = ch >> 3, c8 = ch & 7;
                uint32_t off = kc * (32 * 128) + row * 128 + ((c8 ^ (row & 7)) * 16);
                CP_ASYNC16(sHhi + off, h2hi_q + row * HH2 + ch * 8);
                CP_ASYNC16(sHlo + off, h2lo_q + row * HH2 + ch * 8);
            }
            CP_COMMIT(); CP_WAIT0();
            __syncthreads();

            float acc[2][4];
#pragma unroll
            for (int nt = 0; nt < 2; nt++)
#pragma unroll
                for (int j = 0; j < 4; j++) acc[nt][j] = 0.f;

#pragma unroll 4
            for (int ks = 0; ks < 32; ks++) {
                const int kc = ks >> 2;
                uint32_t ah[4], al[4], bh[4], blo[4];
                {
                    int ch = 2 * (ks & 3) + ahalf;
                    uint32_t off = kc * (32 * 128) + arow * 128 + ((ch ^ (arow & 7)) * 16);
                    LDSM_X4(ah, sHhi + off);
                    LDSM_X4(al, sHlo + off);
                }
                {
                    int ch = 2 * (ks & 3) + bhalf;
                    uint32_t off = kc * (64 * 128) + brow * 128 + ((ch ^ (brow & 7)) * 16);
                    LDSM_X4(bh, sWhi + off);
                    LDSM_X4(blo, sWlo + off);
                }
#pragma unroll
                for (int nt = 0; nt < 2; nt++) {
                    MMA16816H(acc[nt], ah, bh[nt * 2], bh[nt * 2 + 1]);
                    MMA16816H(acc[nt], ah, blo[nt * 2], blo[nt * 2 + 1]);
                    MMA16816H(acc[nt], al, bh[nt * 2], bh[nt * 2 + 1]);
                }
            }

#pragma unroll
            for (int nt = 0; nt < 2; nt++) {
                int col = wn * 16 + nt * 8 + (lane & 3) * 2;
                int row = wm * 16 + (lane >> 2);
                G[col * 33 + row]           = acc[nt][0];
                G[(col + 1) * 33 + row]     = acc[nt][1];
                G[col * 33 + row + 8]       = acc[nt][2];
                G[(col + 1) * 33 + row + 8] = acc[nt][3];
            }
            __syncthreads();
        }

        float aA[4] = {0, 0, 0, 0}, aB[4] = {0, 0, 0, 0};
        if (t > 0) {
#pragma unroll
            for (int g = 0; g < 4; g++) {
                aA[g] = G[(g * 16 + u) * 33 + bb];
                aB[g] = G[(g * 16 + u) * 33 + bb + 16];
            }
        }

        {
            float gi = pA[0] + aA[0], gf = pA[1] + aA[1];
            float gg = pA[2] + aA[2], go = pA[3] + aA[3];
            float si = 1.f / (1.f + __expf(-gi));
            float sf = 1.f / (1.f + __expf(-gf));
            float so = 1.f / (1.f + __expf(-go));
            float tg = tanhf(gg);
            c0 = sf * c0 + si * tg;
            float h = so * tanhf(c0);
            out[((size_t)t * BATCH + b0 + bb) * HH2 + u0 + u] = h;
            __half hb = __float2half_rn(h);
            h2hi_q[bb * HH2 + u0 + u] = hb;
            h2lo_q[bb * HH2 + u0 + u] = __float2half_rn(h - __half2float(hb));
        }
        {
            float gi = pB[0] + aB[0], gf = pB[1] + aB[1];
            float gg = pB[2] + aB[2], go = pB[3] + aB[3];
            float si = 1.f / (1.f + __expf(-gi));
            float sf = 1.f / (1.f + __expf(-gf));
            float so = 1.f / (1.f + __expf(-go));
            float tg = tanhf(gg);
            c1 = sf * c1 + si * tg;
            float h = so * tanhf(c1);
            out[((size_t)t * BATCH + b0 + bb + 16) * HH2 + u0 + u] = h;
            __half hb = __float2half_rn(h);
            h2hi_q[(bb + 16) * HH2 + u0 + u] = hb;
            h2lo_q[(bb + 16) * HH2 + u0 + u] = __float2half_rn(h - __half2float(hb));
        }

        if (t < T_STEPS - 1)
            grid_sync_q(lgen, &g_bcnt[bq * 32], &g_bgen[bq * 32], 32);
    }
}

// ---------------------------------------------------------------------------
extern "C" void kernel_launch(void* const* d_in, const int* in_sizes, int n_in,
                              void* d_out, int out_size)
{
    const float* inp  = (const float*)d_in[0];
    const float* Wih1 = (const float*)d_in[1];
    const float* Whh1 = (const float*)d_in[2];
    const float* b1   = (const float*)d_in[3];
    const float* Wih2 = (const float*)d_in[4];
    const float* Whh2 = (const float*)d_in[5];
    const float* b2   = (const float*)d_in[6];
    float* out = (float*)d_out;

    float *pre1, *pre2;
    cudaGetSymbolAddress((void**)&pre1, g_pre1);
    cudaGetSymbolAddress((void**)&pre2, g_pre2);

    __half *ahi, *alo, *wf, *y1hi, *y1lo, *w2f, *h2hi, *h2lo;
    cudaGetSymbolAddress((void**)&ahi,  g_Ahi);
    cudaGetSymbolAddress((void**)&alo,  g_Alo);
    cudaGetSymbolAddress((void**)&wf,   g_Wf);
    cudaGetSymbolAddress((void**)&y1hi, g_Y1hi);
    cudaGetSymbolAddress((void**)&y1lo, g_Y1lo);
    cudaGetSymbolAddress((void**)&w2f,  g_W2f);
    cudaGetSymbolAddress((void**)&h2hi, g_H2hi);
    cudaGetSymbolAddress((void**)&h2lo, g_H2lo);

    cudaFuncSetAttribute(gemm_mma_f16,
                         cudaFuncAttributeMaxDynamicSharedMemorySize, GEMM_SMEM);
    cudaFuncSetAttribute(lstm_rec1_mma,
                         cudaFuncAttributeMaxDynamicSharedMemorySize, REC1_SMEM);
    cudaFuncSetAttribute(lstm_rec2_mma,
                         cudaFuncAttributeMaxDynamicSharedMemorySize, REC2_SMEM);

    const int M = T_STEPS * BATCH;  // 2048

    // splits: inp -> fp16 (hi,lo); Wih1, Wih2 -> fp16
    {
        int n4a = M * IN_DIM / 4;
        split_f16<<<(n4a + 255) / 256, 256>>>(inp, ahi, alo, n4a);
        int n4w = 4 * HH1 * IN_DIM / 4;
        conv_f16<<<(n4w + 255) / 256, 256>>>(Wih1, wf, n4w);
        int n4w2 = 4 * HH2 * HH1 / 4;
        conv_f16<<<(n4w2 + 255) / 256, 256>>>(Wih2, w2f, n4w2);
    }

    // Layer 1 input projection (fp16 2-pass, BM64/BN128): pre1 = X @ Wih1^T + b1
    gemm_mma_f16<<<dim3(4 * HH1 / 128, M / 64), 128, GEMM_SMEM>>>(
        ahi, alo, wf, b1, pre1, 4 * HH1, IN_DIM);

    // Layer 1 recurrence (persistent, tensorized; emits y1 fp16 hi/lo only)
    lstm_rec1_mma<<<128, 256, REC1_SMEM>>>(pre1, Whh1, y1hi, y1lo);

    // Layer 2 input projection (K=256): pre2 = Y1 @ Wih2^T + b2
    gemm_mma_f16<<<dim3(4 * HH2 / 128, M / 64), 128, GEMM_SMEM>>>(
        y1hi, y1lo, w2f, b2, pre2, 4 * HH2, HH1);

    // Layer 2 recurrence (persistent, tensorized; h written straight into d_out)
    lstm_rec2_mma<<<128, 256, REC2_SMEM>>>(pre2, Whh2, out, h2hi, h2lo);
}

// round 15
// speedup vs baseline: 1.2912x; 1.2912x over previous
#include <cuda_runtime.h>
#include <cuda_fp16.h>
#include <cstdint>
#include <math.h>

#define T_STEPS 16
#define BATCH   128
#define IN_DIM  12288
#define HH1     256
#define HH2     512

// ---------------- scratch (static __device__ globals; no runtime alloc) ----
__device__ float g_pre1[T_STEPS * BATCH * 4 * HH1];   //  8.4 MB
__device__ float g_y1  [T_STEPS * BATCH * HH1];       //  2.1 MB
__device__ float g_pre2[T_STEPS * BATCH * 4 * HH2];   // 16.8 MB

// fp16 staging: A split (hi,lo), W rounded once
__device__ __half g_Ahi[T_STEPS * BATCH * IN_DIM];    // 50 MB
__device__ __half g_Alo[T_STEPS * BATCH * IN_DIM];    // 50 MB
__device__ __half g_Wf [4 * HH1 * IN_DIM];            // 25 MB
__device__ __half g_Y1hi[T_STEPS * BATCH * HH1];      //  1 MB
__device__ __half g_Y1lo[T_STEPS * BATCH * HH1];      //  1 MB
__device__ __half g_W2f[4 * HH2 * HH1];               //  1 MB

// per-quarter h staging for tensorized layer-2 recurrence
__device__ __half g_H2hi[4 * 32 * HH2];
__device__ __half g_H2lo[4 * 32 * HH2];

// quarter-local barrier state (stride 32 u32 = 128 B to avoid false sharing)
__device__ unsigned g_bcnt[4 * 32];
__device__ unsigned g_bgen[4 * 32];

// ===========================================================================
// helpers
// ===========================================================================
__device__ __forceinline__ uint32_t smem_u32(const void* p) {
    uint32_t a;
    asm("{ .reg .u64 t; cvta.to.shared.u64 t, %1; cvt.u32.u64 %0, t; }"
        : "=r"(a) : "l"(p));
    return a;
}

#define LDSM_X4(r, addr) \
    asm volatile("ldmatrix.sync.aligned.m8n8.x4.shared.b16 {%0,%1,%2,%3}, [%4];" \
        : "=r"((r)[0]), "=r"((r)[1]), "=r"((r)[2]), "=r"((r)[3]) : "r"(addr))

#define MMA16816H(d, a, b0v, b1v) \
    asm volatile("mma.sync.aligned.m16n8k16.row.col.f32.f16.f16.f32 " \
        "{%0,%1,%2,%3}, {%4,%5,%6,%7}, {%8,%9}, {%0,%1,%2,%3};" \
        : "+f"((d)[0]), "+f"((d)[1]), "+f"((d)[2]), "+f"((d)[3]) \
        : "r"((a)[0]), "r"((a)[1]), "r"((a)[2]), "r"((a)[3]), \
          "r"(b0v), "r"(b1v))

#define CP_ASYNC16(dst, src) \
    asm volatile("cp.async.cg.shared.global [%0], [%1], 16;" \
        :: "r"(dst), "l"(src))
#define CP_COMMIT() asm volatile("cp.async.commit_group;" ::: "memory")
#define CP_WAIT0()  asm volatile("cp.async.wait_group 0;"  ::: "memory")
#define CP_WAIT1()  asm volatile("cp.async.wait_group 1;"  ::: "memory")

// packed dual-FMA: d.lo += a.lo*b.lo ; d.hi += a.hi*b.hi  (Blackwell f32x2)
#define FMA_F32X2(d, a, b) \
    asm("fma.rn.f32x2 %0, %1, %2, %0;" : "+l"(d) : "l"(a), "l"(b))

__device__ __forceinline__ float unpack_sum(unsigned long long v) {
    return __uint_as_float((unsigned)(v & 0xffffffffull)) +
           __uint_as_float((unsigned)(v >> 32));
}

// quarter-local device barrier over nblocks co-resident blocks
__device__ __forceinline__ void grid_sync_q(unsigned& lgen, unsigned* cnt,
                                            unsigned* gen, int nblocks) {
    __syncthreads();
    if (threadIdx.x == 0) {
        __threadfence();
        unsigned a = atomicAdd(cnt, 1);
        if (a == (unsigned)(nblocks - 1)) {
            *cnt = 0;
            __threadfence();
            atomicAdd(gen, 1);
        } else {
            while (*(volatile unsigned*)gen <= lgen) { }
            __threadfence();
        }
        lgen++;
    }
    __syncthreads();
}

// ===========================================================================
// fp32 -> (hi, lo) fp16 split / fp32 -> fp16 round
// ===========================================================================
__global__ __launch_bounds__(256)
void split_f16(const float* __restrict__ x, __half* __restrict__ hi,
               __half* __restrict__ lo, int n4) {
    int i = blockIdx.x * blockDim.x + threadIdx.x;
    if (i >= n4) return;
    float4 v = ((const float4*)x)[i];
    float vv[4] = {v.x, v.y, v.z, v.w};
    __align__(8) __half h[4], l[4];
#pragma unroll
    for (int j = 0; j < 4; j++) {
        h[j] = __float2half_rn(vv[j]);
        l[j] = __float2half_rn(vv[j] - __half2float(h[j]));
    }
    ((uint2*)hi)[i] = *(uint2*)h;
    ((uint2*)lo)[i] = *(uint2*)l;
}

__global__ __launch_bounds__(256)
void conv_f16(const float* __restrict__ x, __half* __restrict__ w, int n4) {
    int i = blockIdx.x * blockDim.x + threadIdx.x;
    if (i >= n4) return;
    float4 v = ((const float4*)x)[i];
    __align__(8) __half h[4] = { __float2half_rn(v.x), __float2half_rn(v.y),
                                 __float2half_rn(v.z), __float2half_rn(v.w) };
    ((uint2*)w)[i] = *(uint2*)h;
}

// ===========================================================================
// fp16 2-pass GEMM on mma.sync:  C[M,N] = (Ahi+Alo)[M,K] @ Wf[N,K]^T + bias[N]
// 128x64 CTA tile, 256 threads (8 warps as 4m x 2n, warp tile 32x32),
// 2 CTAs/SM -> 16 warps/SM. BK=64 (128B rows, XOR-8 swizzle), 2-stage
// cp.async (40 KB/stage). 2 fp16 passes (A hi + A lo vs single W).
// ===========================================================================
#define A_T_BYTES  16384                 // 128x64 fp16
#define W_T_BYTES  8192                  // 64x64 fp16
#define STAGE_B    (2 * A_T_BYTES + W_T_BYTES)       // 40 KB
#define GEMM_SMEM  (2 * STAGE_B)                     // 80 KB

__global__ __launch_bounds__(256, 2)
void gemm_mma_f16(const __half* __restrict__ Ahi,
                  const __half* __restrict__ Alo,
                  const __half* __restrict__ Wf,
                  const float* __restrict__ bias,
                  float* __restrict__ C,
                  int N, int K)
{
    extern __shared__ __align__(1024) char smem[];
    const uint32_t sb = smem_u32(smem);

    const int tid  = threadIdx.x;
    const int lane = tid & 31;
    const int wid  = tid >> 5;
    const int wm   = wid & 3;            // 4 m strips (32 rows each)
    const int wn   = wid >> 2;           // 2 n strips (32 cols each)
    const int bm0 = blockIdx.y * 128;
    const int bn0 = blockIdx.x * 64;

    const __half* srcA[2] = { Ahi + (size_t)bm0 * K,  Alo + (size_t)bm0 * K };
    const __half* srcW    =   Wf  + (size_t)bn0 * K;

    const int NC = K / 64;

    auto issue_stage = [&](int kc, int stage) {
        const size_t koff = (size_t)kc * 64;
        const uint32_t stb = sb + stage * STAGE_B;
        // A tiles: 128 rows -> 1024 16B chunks each; 4 iters of 256 threads
#pragma unroll
        for (int t = 0; t < 2; t++) {
            const uint32_t tb = stb + t * A_T_BYTES;
#pragma unroll
            for (int i = 0; i < 4; i++) {
                int idx = tid + i * 256;
                int rr = idx >> 3, c16 = idx & 7;
                const __half* src = srcA[t] + (size_t)rr * K + koff + c16 * 8;
                CP_ASYNC16(tb + rr * 128 + ((c16 ^ (rr & 7)) * 16), src);
            }
        }
        // W tile: 64 rows -> 512 chunks; 2 iters
        {
            const uint32_t tb = stb + 2 * A_T_BYTES;
#pragma unroll
            for (int i = 0; i < 2; i++) {
                int idx = tid + i * 256;
                int rr = idx >> 3, c16 = idx & 7;
                const __half* src = srcW + (size_t)rr * K + koff + c16 * 8;
                CP_ASYNC16(tb + rr * 128 + ((c16 ^ (rr & 7)) * 16), src);
            }
        }
    };

    float acc[2][4][4];
#pragma unroll
    for (int mt = 0; mt < 2; mt++)
#pragma unroll
        for (int nt = 0; nt < 4; nt++)
#pragma unroll
            for (int j = 0; j < 4; j++)
                acc[mt][nt][j] = 0.f;

    const int arow  = wm * 32 + (lane & 15);
    const int ahalf = lane >> 4;
    const int brow  = wn * 32 + ((lane >> 4) << 3) + (lane & 7);
    const int bhalf = (lane >> 3) & 1;

    issue_stage(0, 0); CP_COMMIT();

#pragma unroll 1
    for (int kc = 0; kc < NC; kc++) {
        if (kc + 1 < NC) issue_stage(kc + 1, (kc + 1) & 1);
        CP_COMMIT();
        CP_WAIT1();
        __syncthreads();

        const uint32_t stb = sb + (kc & 1) * STAGE_B;
        const uint32_t tAh = stb;
        const uint32_t tAl = stb + A_T_BYTES;
        const uint32_t tW  = stb + 2 * A_T_BYTES;

#pragma unroll
        for (int ks = 0; ks < 4; ks++) {
            uint32_t ahi[2][4], alo[2][4], bf[2][4];
#pragma unroll
            for (int mt = 0; mt < 2; mt++) {
                int rr = arow + mt * 16;
                int ch = 2 * ks + ahalf;
                uint32_t off = rr * 128 + ((ch ^ (rr & 7)) * 16);
                LDSM_X4(ahi[mt], tAh + off);
                LDSM_X4(alo[mt], tAl + off);
            }
#pragma unroll
            for (int nt2 = 0; nt2 < 2; nt2++) {
                int r  = brow + nt2 * 16;
                int ch = 2 * ks + bhalf;
                uint32_t off = r * 128 + ((ch ^ (r & 7)) * 16);
                LDSM_X4(bf[nt2], tW + off);
            }
#pragma unroll
            for (int mt = 0; mt < 2; mt++)
#pragma unroll
                for (int nt = 0; nt < 4; nt++) {
                    const uint32_t* bv = &bf[nt >> 1][(nt & 1) * 2];
                    MMA16816H(acc[mt][nt], ahi[mt], bv[0], bv[1]);
                    MMA16816H(acc[mt][nt], alo[mt], bv[0], bv[1]);
                }
        }
        __syncthreads();
    }

#pragma unroll
    for (int mt = 0; mt < 2; mt++) {
        int row0 = bm0 + wm * 32 + mt * 16 + (lane >> 2);
#pragma unroll
        for (int nt = 0; nt < 4; nt++) {
            int col = bn0 + wn * 32 + nt * 8 + (lane & 3) * 2;
            float b0 = bias[col], b1 = bias[col + 1];
            float2 o0 = { acc[mt][nt][0] + b0, acc[mt][nt][1] + b1 };
            float2 o1 = { acc[mt][nt][2] + b0, acc[mt][nt][3] + b1 };
            *(float2*)&C[(size_t)row0 * N + col]       = o0;
            *(float2*)&C[(size_t)(row0 + 8) * N + col] = o1;
        }
    }
}

// ===========================================================================
// Persistent layer-1 recurrence (scalar f32x2, proven R12 version)
// ===========================================================================
#define REC1_SMEM ((32 * 260 + 32 * 260) * 4)   // 66560 B

__global__ __launch_bounds__(256, 1)
void lstm_rec1(const float* __restrict__ pre,   // [16][128][1024]
               const float* __restrict__ Whh,   // [1024][256]
               float* __restrict__ y1,          // [16][128][256]
               __half* __restrict__ y1hi,
               __half* __restrict__ y1lo)
{
    extern __shared__ __align__(1024) float sm1[];
    float* ws = sm1;                  // [32][260]
    float* hs = sm1 + 32 * 260;       // [32][260]
    const uint32_t hs_b = smem_u32(hs);

    const int tid = threadIdx.x;
    const int bq  = blockIdx.x >> 5;
    const int ug  = blockIdx.x & 31;
    const int u0  = ug * 8;
    const int b0  = bq * 32;

    const int u  = tid & 7;
    const int bl = tid >> 3;

    for (int i = tid; i < 32 * 256; i += 256) {
        int lr = i >> 8, k = i & 255;
        int g = lr >> 3, uu = lr & 7;
        ws[lr * 260 + k] = Whh[(size_t)(g * HH1 + u0 + uu) * HH1 + k];
    }
    unsigned lgen = 0;
    if (tid == 0) lgen = *(volatile unsigned*)&g_bgen[bq * 32];
    __syncthreads();

    const ulonglong2* h2 = (const ulonglong2*)(hs + bl * 260);
    const ulonglong2* w2[4];
#pragma unroll
    for (int g = 0; g < 4; g++)
        w2[g] = (const ulonglong2*)(ws + (g * 8 + u) * 260);

    float c = 0.f;

#pragma unroll 1
    for (int t = 0; t < T_STEPS; t++) {
        const float* prow = pre + ((size_t)t * BATCH + b0 + bl) * (4 * HH1) + u0 + u;
        float p0 = prow[0], p1 = prow[HH1], p2 = prow[2 * HH1], p3 = prow[3 * HH1];

        float a0 = 0.f, a1 = 0.f, a2 = 0.f, a3 = 0.f;
        if (t > 0) {
            const float* hsrc = y1 + (size_t)(t - 1) * BATCH * HH1 + (size_t)b0 * HH1;
#pragma unroll
            for (int i = 0; i < 8; i++) {
                int flat = tid + i * 256;
                int row = flat >> 6;
                int c16 = flat & 63;
                CP_ASYNC16(hs_b + row * 1040 + c16 * 16,
                           hsrc + row * HH1 + c16 * 4);
            }
            CP_COMMIT(); CP_WAIT0();
            __syncthreads();

            unsigned long long acc2[4][2] = {{0,0},{0,0},{0,0},{0,0}};
#pragma unroll 8
            for (int k4 = 0; k4 < 64; k4++) {
                ulonglong2 hv = h2[k4];
#pragma unroll
                for (int g = 0; g < 4; g++) {
                    ulonglong2 wv = w2[g][k4];
                    FMA_F32X2(acc2[g][0], hv.x, wv.x);
                    FMA_F32X2(acc2[g][1], hv.y, wv.y);
                }
            }
            a0 = unpack_sum(acc2[0][0]) + unpack_sum(acc2[0][1]);
            a1 = unpack_sum(acc2[1][0]) + unpack_sum(acc2[1][1]);
            a2 = unpack_sum(acc2[2][0]) + unpack_sum(acc2[2][1]);
            a3 = unpack_sum(acc2[3][0]) + unpack_sum(acc2[3][1]);
        }

        float gi = p0 + a0, gf = p1 + a1, gg = p2 + a2, go = p3 + a3;
        float si = 1.f / (1.f + __expf(-gi));
        float sf = 1.f / (1.f + __expf(-gf));
        float so = 1.f / (1.f + __expf(-go));
        float tg = tanhf(gg);
        c = sf * c + si * tg;
        float h = so * tanhf(c);

        size_t oi = ((size_t)t * BATCH + b0 + bl) * HH1 + u0 + u;
        y1[oi] = h;
        __half hb = __float2half_rn(h);
        y1hi[oi] = hb;
        y1lo[oi] = __float2half_rn(h - __half2float(hb));

        if (t < T_STEPS - 1)
            grid_sync_q(lgen, &g_bcnt[bq * 32], &g_bgen[bq * 32], 32);
    }
}

// ===========================================================================
// Persistent layer-2 recurrence, TENSORIZED (proven R12 version)
// ===========================================================================
#define RC2_W_B (8 * 64 * 128)           // 64 KB per W component
#define RC2_H_B (8 * 32 * 128)           // 32 KB per h component
#define REC2_SMEM (2 * RC2_W_B + 2 * RC2_H_B + 64 * 33 * 4)   // 205056 B

__global__ __launch_bounds__(256, 1)
void lstm_rec2_mma(const float* __restrict__ pre,   // [16][128][2048]
                   const float* __restrict__ Whh,   // [2048][512]
                   float* __restrict__ out,         // [16][128][512]
                   __half* __restrict__ h2hi,       // [4][32][512]
                   __half* __restrict__ h2lo)
{
    extern __shared__ __align__(1024) char sm2[];
    const uint32_t sb   = smem_u32(sm2);
    const uint32_t sWhi = sb;
    const uint32_t sWlo = sb + RC2_W_B;
    const uint32_t sHhi = sb + 2 * RC2_W_B;
    const uint32_t sHlo = sb + 2 * RC2_W_B + RC2_H_B;
    float* G = (float*)(sm2 + 2 * RC2_W_B + 2 * RC2_H_B);   // [64][33]

    const int tid  = threadIdx.x;
    const int lane = tid & 31;
    const int wid  = tid >> 5;
    const int wm   = wid & 1;
    const int wn   = wid >> 1;
    const int bq   = blockIdx.x >> 5;
    const int ug   = blockIdx.x & 31;
    const int u0   = ug * 16;
    const int b0   = bq * 32;

    __half* h2hi_q = h2hi + (size_t)bq * 32 * HH2;
    __half* h2lo_q = h2lo + (size_t)bq * 32 * HH2;

    for (int i = tid; i < 4096; i += 256) {
        int r  = i >> 6;
        int ch = i & 63;
        int g = r >> 4, uu = r & 15;
        const float* wsrc = Whh + (size_t)(g * HH2 + u0 + uu) * HH2 + ch * 8;
        __align__(16) __half hi8[8], lo8[8];
#pragma unroll
        for (int j = 0; j < 8; j++) {
            float f = wsrc[j];
            hi8[j] = __float2half_rn(f);
            lo8[j] = __float2half_rn(f - __half2float(hi8[j]));
        }
        int kc = ch >> 3, c8 = ch & 7;
        uint32_t off = kc * (64 * 128) + r * 128 + ((c8 ^ (r & 7)) * 16);
        *(uint4*)(sm2 + (sWhi - sb) + off) = *(uint4*)hi8;
        *(uint4*)(sm2 + (sWlo - sb) + off) = *(uint4*)lo8;
    }
    unsigned lgen = 0;
    if (tid == 0) lgen = *(volatile unsigned*)&g_bgen[bq * 32];
    __syncthreads();

    const int u  = tid & 15;
    const int bb = tid >> 4;
    float c0 = 0.f, c1 = 0.f;

    const int arow  = wm * 16 + (lane & 15);
    const int ahalf = lane >> 4;
    const int brow  = wn * 16 + ((lane >> 4) << 3) + (lane & 7);
    const int bhalf = (lane >> 3) & 1;

#pragma unroll 1
    for (int t = 0; t < T_STEPS; t++) {
        const float* prowA = pre + ((size_t)t * BATCH + b0 + bb) * (4 * HH2) + u0 + u;
        const float* prowB = prowA + (size_t)16 * 4 * HH2;
        float pA[4], pB[4];
#pragma unroll
        for (int g = 0; g < 4; g++) { pA[g] = prowA[g * HH2]; pB[g] = prowB[g * HH2]; }

        if (t > 0) {
#pragma unroll
            for (int i = 0; i < 8; i++) {
                int flat = tid + i * 256;
                int row = flat >> 6;
                int ch  = flat & 63;
                int kc = ch >> 3, c8 = ch & 7;
                uint32_t off = kc * (32 * 128) + row * 128 + ((c8 ^ (row & 7)) * 16);
                CP_ASYNC16(sHhi + off, h2hi_q + row * HH2 + ch * 8);
                CP_ASYNC16(sHlo + off, h2lo_q + row * HH2 + ch * 8);
            }
            CP_COMMIT(); CP_WAIT0();
            __syncthreads();

            float acc[2][4];
#pragma unroll
            for (int nt = 0; nt < 2; nt++)
#pragma unroll
                for (int j = 0; j < 4; j++) acc[nt][j] = 0.f;

#pragma unroll 4
            for (int ks = 0; ks < 32; ks++) {
                const int kc = ks >> 2;
                uint32_t ah[4], al[4], bh[4], blo[4];
                {
                    int ch = 2 * (ks & 3) + ahalf;
                    uint32_t off = kc * (32 * 128) + arow * 128 + ((ch ^ (arow & 7)) * 16);
                    LDSM_X4(ah, sHhi + off);
                    LDSM_X4(al, sHlo + off);
                }
                {
                    int ch = 2 * (ks & 3) + bhalf;
                    uint32_t off = kc * (64 * 128) + brow * 128 + ((ch ^ (brow & 7)) * 16);
                    LDSM_X4(bh, sWhi + off);
                    LDSM_X4(blo, sWlo + off);
                }
#pragma unroll
                for (int nt = 0; nt < 2; nt++) {
                    MMA16816H(acc[nt], ah, bh[nt * 2], bh[nt * 2 + 1]);
                    MMA16816H(acc[nt], ah, blo[nt * 2], blo[nt * 2 + 1]);
                    MMA16816H(acc[nt], al, bh[nt * 2], bh[nt * 2 + 1]);
                }
            }

#pragma unroll
            for (int nt = 0; nt < 2; nt++) {
                int col = wn * 16 + nt * 8 + (lane & 3) * 2;
                int row = wm * 16 + (lane >> 2);
                G[col * 33 + row]           = acc[nt][0];
                G[(col + 1) * 33 + row]     = acc[nt][1];
                G[col * 33 + row + 8]       = acc[nt][2];
                G[(col + 1) * 33 + row + 8] = acc[nt][3];
            }
            __syncthreads();
        }

        float aA[4] = {0, 0, 0, 0}, aB[4] = {0, 0, 0, 0};
        if (t > 0) {
#pragma unroll
            for (int g = 0; g < 4; g++) {
                aA[g] = G[(g * 16 + u) * 33 + bb];
                aB[g] = G[(g * 16 + u) * 33 + bb + 16];
            }
        }

        {
            float gi = pA[0] + aA[0], gf = pA[1] + aA[1];
            float gg = pA[2] + aA[2], go = pA[3] + aA[3];
            float si = 1.f / (1.f + __expf(-gi));
            float sf = 1.f / (1.f + __expf(-gf));
            float so = 1.f / (1.f + __expf(-go));
            float tg = tanhf(gg);
            c0 = sf * c0 + si * tg;
            float h = so * tanhf(c0);
            out[((size_t)t * BATCH + b0 + bb) * HH2 + u0 + u] = h;
            __half hb = __float2half_rn(h);
            h2hi_q[bb * HH2 + u0 + u] = hb;
            h2lo_q[bb * HH2 + u0 + u] = __float2half_rn(h - __half2float(hb));
        }
        {
            float gi = pB[0] + aB[0], gf = pB[1] + aB[1];
            float gg = pB[2] + aB[2], go = pB[3] + aB[3];
            float si = 1.f / (1.f + __expf(-gi));
            float sf = 1.f / (1.f + __expf(-gf));
            float so = 1.f / (1.f + __expf(-go));
            float tg = tanhf(gg);
            c1 = sf * c1 + si * tg;
            float h = so * tanhf(c1);
            out[((size_t)t * BATCH + b0 + bb + 16) * HH2 + u0 + u] = h;
            __half hb = __float2half_rn(h);
            h2hi_q[(bb + 16) * HH2 + u0 + u] = hb;
            h2lo_q[(bb + 16) * HH2 + u0 + u] = __float2half_rn(h - __half2float(hb));
        }

        if (t < T_STEPS - 1)
            grid_sync_q(lgen, &g_bcnt[bq * 32], &g_bgen[bq * 32], 32);
    }
}

// ---------------------------------------------------------------------------
extern "C" void kernel_launch(void* const* d_in, const int* in_sizes, int n_in,
                              void* d_out, int out_size)
{
    const float* inp  = (const float*)d_in[0];
    const float* Wih1 = (const float*)d_in[1];
    const float* Whh1 = (const float*)d_in[2];
    const float* b1   = (const float*)d_in[3];
    const float* Wih2 = (const float*)d_in[4];
    const float* Whh2 = (const float*)d_in[5];
    const float* b2   = (const float*)d_in[6];
    float* out = (float*)d_out;

    float *pre1, *y1, *pre2;
    cudaGetSymbolAddress((void**)&pre1, g_pre1);
    cudaGetSymbolAddress((void**)&y1,   g_y1);
    cudaGetSymbolAddress((void**)&pre2, g_pre2);

    __half *ahi, *alo, *wf, *y1hi, *y1lo, *w2f, *h2hi, *h2lo;
    cudaGetSymbolAddress((void**)&ahi,  g_Ahi);
    cudaGetSymbolAddress((void**)&alo,  g_Alo);
    cudaGetSymbolAddress((void**)&wf,   g_Wf);
    cudaGetSymbolAddress((void**)&y1hi, g_Y1hi);
    cudaGetSymbolAddress((void**)&y1lo, g_Y1lo);
    cudaGetSymbolAddress((void**)&w2f,  g_W2f);
    cudaGetSymbolAddress((void**)&h2hi, g_H2hi);
    cudaGetSymbolAddress((void**)&h2lo, g_H2lo);

    cudaFuncSetAttribute(gemm_mma_f16,
                         cudaFuncAttributeMaxDynamicSharedMemorySize, GEMM_SMEM);
    cudaFuncSetAttribute(lstm_rec1,
                         cudaFuncAttributeMaxDynamicSharedMemorySize, REC1_SMEM);
    cudaFuncSetAttribute(lstm_rec2_mma,
                         cudaFuncAttributeMaxDynamicSharedMemorySize, REC2_SMEM);

    const int M = T_STEPS * BATCH;  // 2048

    // splits: inp -> fp16 (hi,lo); Wih1, Wih2 -> fp16
    {
        int n4a = M * IN_DIM / 4;
        split_f16<<<(n4a + 255) / 256, 256>>>(inp, ahi, alo, n4a);
        int n4w = 4 * HH1 * IN_DIM / 4;
        conv_f16<<<(n4w + 255) / 256, 256>>>(Wih1, wf, n4w);
        int n4w2 = 4 * HH2 * HH1 / 4;
        conv_f16<<<(n4w2 + 255) / 256, 256>>>(Wih2, w2f, n4w2);
    }

    // Layer 1 input projection (fp16 2-pass, BM128/BN64, 256 thr): pre1
    gemm_mma_f16<<<dim3(4 * HH1 / 64, M / 128), 256, GEMM_SMEM>>>(
        ahi, alo, wf, b1, pre1, 4 * HH1, IN_DIM);

    // Layer 1 recurrence (persistent scalar, emits y1 fp16 hi/lo)
    lstm_rec1<<<128, 256, REC1_SMEM>>>(pre1, Whh1, y1, y1hi, y1lo);

    // Layer 2 input projection (K=256): pre2 = Y1 @ Wih2^T + b2
    gemm_mma_f16<<<dim3(4 * HH2 / 64, M / 128), 256, GEMM_SMEM>>>(
        y1hi, y1lo, w2f, b2, pre2, 4 * HH2, HH1);

    // Layer 2 recurrence (persistent, tensorized; h written straight into d_out)
    lstm_rec2_mma<<<128, 256, REC2_SMEM>>>(pre2, Whh2, out, h2hi, h2lo);
}